// round 3
// baseline (speedup 1.0000x reference)
#include <cuda_runtime.h>
#include <math.h>

#define TT 4096
#define BB 32
#define DD 128
#define D3 384

// Scratch for xi = x @ Wi + bi : [T, B, 3D] fp32 = 201 MB.
__device__ float g_xi[(size_t)TT * BB * D3];
__device__ int g_reset_mode; // 0 = int32, 1 = float32, 2 = uint8/bool

// ---------------------------------------------------------------------------
// Probe resets dtype (reads 128 KB — in-bounds for every candidate layout).
// ---------------------------------------------------------------------------
__global__ void probe_resets_kernel(const unsigned int* __restrict__ r) {
    __shared__ int s_not01, s_notf;
    if (threadIdx.x == 0) { s_not01 = 0; s_notf = 0; }
    __syncthreads();
    int not01 = 0, notf = 0;
    for (int i = threadIdx.x; i < 32768; i += blockDim.x) {
        unsigned v = r[i];
        if (v != 0u && v != 1u) not01 = 1;
        if (v != 0u && v != 0x3F800000u) notf = 1;
    }
    if (not01) atomicOr(&s_not01, 1);
    if (notf)  atomicOr(&s_notf, 1);
    __syncthreads();
    if (threadIdx.x == 0) {
        int mode;
        if (!s_not01)     mode = 0;
        else if (!s_notf) mode = 1;
        else              mode = 2;
        g_reset_mode = mode;
    }
}

__device__ __forceinline__ int read_reset(const void* r, int idx, int mode) {
    if (mode == 0) return ((const int*)r)[idx] != 0;
    if (mode == 1) return ((const float*)r)[idx] != 0.0f;
    return ((const unsigned char*)r)[idx] != 0;
}

__device__ __forceinline__ unsigned long long pack2(float lo, float hi) {
    unsigned long long p;
    asm("mov.b64 %0, {%1, %2};" : "=l"(p) : "f"(lo), "f"(hi));
    return p;
}

__device__ __forceinline__ void fma2(unsigned long long& acc,
                                     unsigned long long a,
                                     unsigned long long b) {
    asm("fma.rn.f32x2 %0, %1, %2, %0;" : "+l"(acc) : "l"(a), "l"(b));
}

__device__ __forceinline__ float hsum2(unsigned long long a) {
    float lo, hi;
    asm("mov.b64 {%0, %1}, %2;" : "=f"(lo), "=f"(hi) : "l"(a));
    return lo + hi;
}

// ---------------------------------------------------------------------------
// xi = x @ Wi + bi. Thread j holds Wi[:,j] packed as 64 f32x2 pairs in regs;
// x rows broadcast from shared; packed fma halves the FMA issue count.
// ---------------------------------------------------------------------------
__global__ __launch_bounds__(384, 1)
void gemm_xi_kernel(const float* __restrict__ x,
                    const float* __restrict__ Wi,
                    const float* __restrict__ bi) {
    __shared__ __align__(16) float xs[2][DD];
    const int j = threadIdx.x;

    unsigned long long w2[64];
#pragma unroll
    for (int k = 0; k < 64; k++)
        w2[k] = pack2(Wi[(2 * k) * D3 + j], Wi[(2 * k + 1) * D3 + j]);
    const float bj = bi[j];

    const int R = TT * BB;
    const int per = (R + gridDim.x - 1) / gridDim.x;
    const int r0 = blockIdx.x * per;
    const int r1 = min(r0 + per, R);

    for (int r = r0; r < r1; r += 2) {
        if (j < 256) {
            int rr = r + (j >> 7);
            int kk = j & 127;
            xs[j >> 7][kk] = (rr < r1) ? x[(size_t)rr * DD + kk] : 0.0f;
        }
        __syncthreads();

        unsigned long long a00 = 0ull, a01 = 0ull, a10 = 0ull, a11 = 0ull;
        const ulonglong2* x0 = (const ulonglong2*)xs[0];
        const ulonglong2* x1 = (const ulonglong2*)xs[1];
#pragma unroll
        for (int k = 0; k < 32; k++) {
            ulonglong2 v0 = x0[k];
            ulonglong2 v1 = x1[k];
            fma2(a00, w2[2 * k],     v0.x);
            fma2(a01, w2[2 * k + 1], v0.y);
            fma2(a10, w2[2 * k],     v1.x);
            fma2(a11, w2[2 * k + 1], v1.y);
        }
        float s0 = bj + hsum2(a00) + hsum2(a01);
        float s1 = bj + hsum2(a10) + hsum2(a11);
        g_xi[(size_t)r * D3 + j] = s0;
        if (r + 1 < r1) g_xi[(size_t)(r + 1) * D3 + j] = s1;
        __syncthreads();
    }
}

// ---------------------------------------------------------------------------
// GRU scan. One CTA per batch element, 384 threads; thread j owns Wh[:,j]
// packed as 64 f32x2 pairs. Per step: packed-fma dot (384 issue-cyc/SMSP),
// hh exchange via shared, gate math on threads 0..127 with MUFU-based
// sigmoid/tanh, double-buffered h.
// ---------------------------------------------------------------------------
__global__ __launch_bounds__(384, 1)
void gru_scan_kernel(const void* __restrict__ resets,
                     const float* __restrict__ Wh,
                     const float* __restrict__ bhn,
                     float* __restrict__ ys) {
    __shared__ __align__(16) float h[2][DD];
    __shared__ float hh[D3];

    const int b = blockIdx.x;
    const int j = threadIdx.x;
    const int d = j & 127;
    const int g = j >> 7;
    const int mode = g_reset_mode;

    unsigned long long w2[64];
#pragma unroll
    for (int k = 0; k < 64; k++)
        w2[k] = pack2(Wh[(2 * k) * D3 + j], Wh[(2 * k + 1) * D3 + j]);
    const float bn = (g == 2) ? bhn[d] : 0.0f;

    if (j < DD) h[0][j] = 0.0f;

    // Prefetch t = 0 operands.
    const float* xi = g_xi;
    size_t base0 = (size_t)b * D3;
    float px = 0.0f, pxn = 0.0f;
    if (g == 0)      { px = xi[base0 + d]; pxn = xi[base0 + 256 + d]; }
    else if (g == 1) { px = xi[base0 + 128 + d]; }
    int rst = read_reset(resets, b, mode);
    __syncthreads();

    int p = 0;
    for (int t = 0; t < TT; t++) {
        // Prefetch step t+1 (hidden behind dot phase).
        float npx = 0.0f, npxn = 0.0f;
        int nrst = 0;
        if (t + 1 < TT) {
            size_t nb = ((size_t)(t + 1) * BB + b) * D3;
            if (g == 0)      { npx = xi[nb + d]; npxn = xi[nb + 256 + d]; }
            else if (g == 1) { npx = xi[nb + 128 + d]; }
            nrst = read_reset(resets, (t + 1) * BB + b, mode);
        }

        // hh[j] = base + <Wh[:,j], h>  (dot skipped on reset)
        unsigned long long a0 = 0ull, a1 = 0ull, a2 = 0ull, a3 = 0ull;
        const ulonglong2* h2 = (const ulonglong2*)h[p];
#pragma unroll
        for (int k = 0; k < 16; k++) {
            ulonglong2 va = h2[2 * k];
            ulonglong2 vb = h2[2 * k + 1];
            fma2(a0, w2[4 * k + 0], va.x);
            fma2(a1, w2[4 * k + 1], va.y);
            fma2(a2, w2[4 * k + 2], vb.x);
            fma2(a3, w2[4 * k + 3], vb.y);
        }
        float dot = (hsum2(a0) + hsum2(a1)) + (hsum2(a2) + hsum2(a3));
        float base = (g == 2) ? bn : px;
        hh[j] = base + (rst ? 0.0f : dot);
        __syncthreads();

        if (j < DD) {
            float sr = hh[d];            // xr + hr
            float sz = hh[128 + d];      // xz + hz
            float sn = hh[256 + d];      // hn + bhn
            float rg = __fdividef(1.0f, 1.0f + __expf(-sr));
            float zg = __fdividef(1.0f, 1.0f + __expf(-sz));
            float ar = pxn + rg * sn;
            float ng = __fdividef(2.0f, 1.0f + __expf(-2.0f * ar)) - 1.0f;
            float hp = rst ? 0.0f : h[p][d];
            float nh = (1.0f - zg) * ng + zg * hp;
            h[p ^ 1][d] = nh;
            ys[((size_t)t * BB + b) * DD + d] = nh;
        }
        __syncthreads();

        p ^= 1;
        px = npx; pxn = npxn; rst = nrst;
    }
}

// ---------------------------------------------------------------------------
extern "C" void kernel_launch(void* const* d_in, const int* in_sizes, int n_in,
                              void* d_out, int out_size) {
    const float* x      = (const float*)d_in[0];
    const void*  resets = d_in[1];
    const float* Wi     = (const float*)d_in[2];
    const float* bi     = (const float*)d_in[3];
    const float* Wh     = (const float*)d_in[4];
    const float* bhn    = (const float*)d_in[5];
    float* ys = (float*)d_out;

    probe_resets_kernel<<<1, 256>>>((const unsigned int*)resets);
    gemm_xi_kernel<<<148, 384>>>(x, Wi, bi);
    gru_scan_kernel<<<BB, 384>>>(resets, Wh, bhn, ys);
}

// round 5
// speedup vs baseline: 1.6992x; 1.6992x over previous
#include <cuda_runtime.h>
#include <math.h>

#define TT 4096
#define BB 32
#define DD 128
#define D3 384
#define NSTAGE 8

// Scratch for xi = x @ Wi + bi : [T, B, 3D] fp32 = 201 MB.
__device__ float g_xi[(size_t)TT * BB * D3];
__device__ int g_reset_mode; // 0 = int32, 1 = float32, 2 = uint8/bool

// ---------------------------------------------------------------------------
// Probe resets dtype (reads 128 KB — in-bounds for every candidate layout).
// ---------------------------------------------------------------------------
__global__ void probe_resets_kernel(const unsigned int* __restrict__ r) {
    __shared__ int s_not01, s_notf;
    if (threadIdx.x == 0) { s_not01 = 0; s_notf = 0; }
    __syncthreads();
    int not01 = 0, notf = 0;
    for (int i = threadIdx.x; i < 32768; i += blockDim.x) {
        unsigned v = r[i];
        if (v != 0u && v != 1u) not01 = 1;
        if (v != 0u && v != 0x3F800000u) notf = 1;
    }
    if (not01) atomicOr(&s_not01, 1);
    if (notf)  atomicOr(&s_notf, 1);
    __syncthreads();
    if (threadIdx.x == 0) {
        int mode;
        if (!s_not01)     mode = 0;
        else if (!s_notf) mode = 1;
        else              mode = 2;
        g_reset_mode = mode;
    }
}

__device__ __forceinline__ int read_reset(const void* r, int idx, int mode) {
    if (mode == 0) return ((const int*)r)[idx] != 0;
    if (mode == 1) return ((const float*)r)[idx] != 0.0f;
    return ((const unsigned char*)r)[idx] != 0;
}

__device__ __forceinline__ unsigned long long pack2(float lo, float hi) {
    unsigned long long p;
    asm("mov.b64 %0, {%1, %2};" : "=l"(p) : "f"(lo), "f"(hi));
    return p;
}

__device__ __forceinline__ void fma2(unsigned long long& acc,
                                     unsigned long long a,
                                     unsigned long long b) {
    asm("fma.rn.f32x2 %0, %1, %2, %0;" : "+l"(acc) : "l"(a), "l"(b));
}

__device__ __forceinline__ float hsum2(unsigned long long a) {
    float lo, hi;
    asm("mov.b64 {%0, %1}, %2;" : "=f"(lo), "=f"(hi) : "l"(a));
    return lo + hi;
}

__device__ __forceinline__ void cp_async16(void* smem_dst, const void* gmem_src) {
    unsigned s = (unsigned)__cvta_generic_to_shared(smem_dst);
    asm volatile("cp.async.cg.shared.global [%0], [%1], 16;"
                 :: "r"(s), "l"(gmem_src) : "memory");
}

// ---------------------------------------------------------------------------
// xi = x @ Wi + bi. Thread j holds Wi[:,j] packed as 64 f32x2 pairs.
// ---------------------------------------------------------------------------
__global__ __launch_bounds__(384, 1)
void gemm_xi_kernel(const float* __restrict__ x,
                    const float* __restrict__ Wi,
                    const float* __restrict__ bi) {
    __shared__ __align__(16) float xs[2][DD];
    const int j = threadIdx.x;

    unsigned long long w2[64];
#pragma unroll
    for (int k = 0; k < 64; k++)
        w2[k] = pack2(Wi[(2 * k) * D3 + j], Wi[(2 * k + 1) * D3 + j]);
    const float bj = bi[j];

    const int R = TT * BB;
    const int per = (R + gridDim.x - 1) / gridDim.x;
    const int r0 = blockIdx.x * per;
    const int r1 = min(r0 + per, R);

    for (int r = r0; r < r1; r += 2) {
        if (j < 256) {
            int rr = r + (j >> 7);
            int kk = j & 127;
            xs[j >> 7][kk] = (rr < r1) ? x[(size_t)rr * DD + kk] : 0.0f;
        }
        __syncthreads();

        unsigned long long a00 = 0ull, a01 = 0ull, a10 = 0ull, a11 = 0ull;
        const ulonglong2* x0 = (const ulonglong2*)xs[0];
        const ulonglong2* x1 = (const ulonglong2*)xs[1];
#pragma unroll
        for (int k = 0; k < 32; k++) {
            ulonglong2 v0 = x0[k];
            ulonglong2 v1 = x1[k];
            fma2(a00, w2[2 * k],     v0.x);
            fma2(a01, w2[2 * k + 1], v0.y);
            fma2(a10, w2[2 * k],     v1.x);
            fma2(a11, w2[2 * k + 1], v1.y);
        }
        float s0 = bj + hsum2(a00) + hsum2(a01);
        float s1 = bj + hsum2(a10) + hsum2(a11);
        g_xi[(size_t)r * D3 + j] = s0;
        if (r + 1 < r1) g_xi[(size_t)(r + 1) * D3 + j] = s1;
        __syncthreads();
    }
}

// ---------------------------------------------------------------------------
// GRU scan. One CTA per batch element, 384 threads.
//  - Wh[:,j] register-resident as 64 f32x2 pairs (thread j owns column j).
//  - xi staged NSTAGE=8 steps ahead via cp.async ring. The refill of slot st
//    is issued AFTER B2 of step t (all readers done) — never aliases a live
//    read. wait_group(NSTAGE-1) at the top guarantees stage t is complete.
//  - resets for this batch preloaded once into shared (4 KB).
// ---------------------------------------------------------------------------
__global__ __launch_bounds__(384, 1)
void gru_scan_kernel(const void* __restrict__ resets,
                     const float* __restrict__ Wh,
                     const float* __restrict__ bhn,
                     float* __restrict__ ys) {
    __shared__ __align__(16) float h[2][DD];
    __shared__ float hh[D3];
    __shared__ __align__(16) float xstage[NSTAGE][D3];
    __shared__ unsigned char srst[TT];

    const int b = blockIdx.x;
    const int j = threadIdx.x;
    const int d = j & 127;
    const int g = j >> 7;
    const int mode = g_reset_mode;

    unsigned long long w2[64];
#pragma unroll
    for (int k = 0; k < 64; k++)
        w2[k] = pack2(Wh[(2 * k) * D3 + j], Wh[(2 * k + 1) * D3 + j]);
    const float bn = (g == 2) ? bhn[d] : 0.0f;

    if (j < DD) h[0][j] = 0.0f;

    // One-time preload of this batch's reset flags (removes per-step LDG).
    for (int t = j; t < TT; t += 384)
        srst[t] = (unsigned char)read_reset(resets, t * BB + b, mode);

    // Prime the xi ring buffer: stages 0..NSTAGE-1 (one group per stage).
    for (int s = 0; s < NSTAGE; s++) {
        if (j < 96)
            cp_async16(&xstage[s][j * 4],
                       g_xi + ((size_t)s * BB + b) * D3 + j * 4);
        asm volatile("cp.async.commit_group;" ::: "memory");
    }
    __syncthreads();

    int p = 0;
    for (int t = 0; t < TT; t++) {
        const int st = t & (NSTAGE - 1);
        const int rst = srst[t];

        // hh[j] = (g==2 ? bhn : 0) + <Wh[:,j], h>, dot skipped on reset.
        unsigned long long a0 = 0ull, a1 = 0ull, a2 = 0ull, a3 = 0ull;
        const ulonglong2* h2 = (const ulonglong2*)h[p];
#pragma unroll
        for (int k = 0; k < 16; k++) {
            ulonglong2 va = h2[2 * k];
            ulonglong2 vb = h2[2 * k + 1];
            fma2(a0, w2[4 * k + 0], va.x);
            fma2(a1, w2[4 * k + 1], va.y);
            fma2(a2, w2[4 * k + 2], vb.x);
            fma2(a3, w2[4 * k + 3], vb.y);
        }
        float dot = (hsum2(a0) + hsum2(a1)) + (hsum2(a2) + hsum2(a3));
        hh[j] = bn + (rst ? 0.0f : dot);

        // Stage t (oldest of the NSTAGE pending groups) must be complete.
        asm volatile("cp.async.wait_group %0;" :: "n"(NSTAGE - 1) : "memory");
        __syncthreads();  // B1: hh + stage st published.

        if (j < DD) {
            const float* xi_s = xstage[st];
            float sr = xi_s[d]       + hh[d];          // xr + hr
            float sz = xi_s[128 + d] + hh[128 + d];    // xz + hz
            float sn = hh[256 + d];                    // hn + bhn
            float rg = __fdividef(1.0f, 1.0f + __expf(-sr));
            float zg = __fdividef(1.0f, 1.0f + __expf(-sz));
            float ar = xi_s[256 + d] + rg * sn;        // xn + r*(hn+bhn)
            float ng = __fdividef(2.0f, 1.0f + __expf(-2.0f * ar)) - 1.0f;
            float hp = rst ? 0.0f : h[p][d];
            float nh = (1.0f - zg) * ng + zg * hp;
            h[p ^ 1][d] = nh;
            ys[((size_t)t * BB + b) * DD + d] = nh;
        }
        __syncthreads();  // B2: new h published; slot st fully consumed.

        // Refill slot st with stage t+NSTAGE (safe: all readers passed B2).
        if (j < 96 && t + NSTAGE < TT)
            cp_async16(&xstage[st][j * 4],
                       g_xi + ((size_t)(t + NSTAGE) * BB + b) * D3 + j * 4);
        asm volatile("cp.async.commit_group;" ::: "memory");

        p ^= 1;
    }
}

// ---------------------------------------------------------------------------
extern "C" void kernel_launch(void* const* d_in, const int* in_sizes, int n_in,
                              void* d_out, int out_size) {
    const float* x      = (const float*)d_in[0];
    const void*  resets = d_in[1];
    const float* Wi     = (const float*)d_in[2];
    const float* bi     = (const float*)d_in[3];
    const float* Wh     = (const float*)d_in[4];
    const float* bhn    = (const float*)d_in[5];
    float* ys = (float*)d_out;

    probe_resets_kernel<<<1, 256>>>((const unsigned int*)resets);
    gemm_xi_kernel<<<148, 384>>>(x, Wi, bi);
    gru_scan_kernel<<<BB, 384>>>(resets, Wh, bhn, ys);
}

// round 6
// speedup vs baseline: 1.9884x; 1.1702x over previous
#include <cuda_runtime.h>

#define TT 4096
#define BB 32
#define DD 128
#define D3 384
#define NSTAGE 8

// Scratch for xi = x @ Wi + bi : [T, B, 3D] fp32 = 201 MB.
__device__ float g_xi[(size_t)TT * BB * D3];
__device__ int g_reset_mode;  // 0 = int32, 1 = float32, 2 = uint8/bool
__device__ int g_ready[TT];   // per-timestep xi completion flags

// ---------------------------------------------------------------------------
// Helpers
// ---------------------------------------------------------------------------
__device__ __forceinline__ int read_reset(const void* r, int idx, int mode) {
    if (mode == 0) return ((const int*)r)[idx] != 0;
    if (mode == 1) return ((const float*)r)[idx] != 0.0f;
    return ((const unsigned char*)r)[idx] != 0;
}

__device__ __forceinline__ unsigned long long pack2(float lo, float hi) {
    unsigned long long p;
    asm("mov.b64 %0, {%1, %2};" : "=l"(p) : "f"(lo), "f"(hi));
    return p;
}

__device__ __forceinline__ void fma2(unsigned long long& acc,
                                     unsigned long long a,
                                     unsigned long long b) {
    asm("fma.rn.f32x2 %0, %1, %2, %0;" : "+l"(acc) : "l"(a), "l"(b));
}

__device__ __forceinline__ float hsum2(unsigned long long a) {
    float lo, hi;
    asm("mov.b64 {%0, %1}, %2;" : "=f"(lo), "=f"(hi) : "l"(a));
    return lo + hi;
}

__device__ __forceinline__ void cp_async16(void* smem_dst, const void* gmem_src) {
    unsigned s = (unsigned)__cvta_generic_to_shared(smem_dst);
    asm volatile("cp.async.cg.shared.global [%0], [%1], 16;"
                 :: "r"(s), "l"(gmem_src) : "memory");
}

__device__ __forceinline__ int ld_acq(const int* p) {
    int v;
    asm volatile("ld.acquire.gpu.b32 %0, [%1];" : "=r"(v) : "l"(p) : "memory");
    return v;
}

__device__ __forceinline__ void st_rel(int* p, int v) {
    asm volatile("st.release.gpu.b32 [%0], %1;" :: "l"(p), "r"(v) : "memory");
}

// ---------------------------------------------------------------------------
// Probe resets dtype (reads 128 KB — in-bounds for every candidate layout)
// and clear the per-timestep ready flags for this replay.
// ---------------------------------------------------------------------------
__global__ void probe_clear_kernel(const unsigned int* __restrict__ r) {
    for (int i = threadIdx.x; i < TT; i += blockDim.x) g_ready[i] = 0;
    __shared__ int s_not01, s_notf;
    if (threadIdx.x == 0) { s_not01 = 0; s_notf = 0; }
    __syncthreads();
    int not01 = 0, notf = 0;
    for (int i = threadIdx.x; i < 32768; i += blockDim.x) {
        unsigned v = r[i];
        if (v != 0u && v != 1u) not01 = 1;
        if (v != 0u && v != 0x3F800000u) notf = 1;
    }
    if (not01) atomicOr(&s_not01, 1);
    if (notf)  atomicOr(&s_notf, 1);
    __syncthreads();
    if (threadIdx.x == 0)
        g_reset_mode = (!s_not01) ? 0 : ((!s_notf) ? 1 : 2);
}

// ---------------------------------------------------------------------------
// GEMM role: blocks 32..grid-1. Block gb owns timesteps t = gb, gb+ngemm, ...
// For each t it computes xi rows [t*32, t*32+32) and publishes g_ready[t].
// ---------------------------------------------------------------------------
__device__ __forceinline__ void gemm_role(const float* __restrict__ x,
                                          const float* __restrict__ Wi,
                                          const float* __restrict__ bi,
                                          int gb, int ngemm) {
    __shared__ __align__(16) float xs[2][DD];
    const int j = threadIdx.x;

    unsigned long long w2[64];
#pragma unroll
    for (int k = 0; k < 64; k++)
        w2[k] = pack2(Wi[(2 * k) * D3 + j], Wi[(2 * k + 1) * D3 + j]);
    const float bj = bi[j];

    for (int t = gb; t < TT; t += ngemm) {
        const int r0 = t * BB;
        for (int rp = 0; rp < BB; rp += 2) {
            const int r = r0 + rp;
            if (j < 256)
                xs[j >> 7][j & 127] = x[(size_t)(r + (j >> 7)) * DD + (j & 127)];
            __syncthreads();

            unsigned long long a00 = 0ull, a01 = 0ull, a10 = 0ull, a11 = 0ull;
            const ulonglong2* x0 = (const ulonglong2*)xs[0];
            const ulonglong2* x1 = (const ulonglong2*)xs[1];
#pragma unroll
            for (int k = 0; k < 32; k++) {
                ulonglong2 v0 = x0[k];
                ulonglong2 v1 = x1[k];
                fma2(a00, w2[2 * k],     v0.x);
                fma2(a01, w2[2 * k + 1], v0.y);
                fma2(a10, w2[2 * k],     v1.x);
                fma2(a11, w2[2 * k + 1], v1.y);
            }
            g_xi[(size_t)r * D3 + j]       = bj + hsum2(a00) + hsum2(a01);
            g_xi[(size_t)(r + 1) * D3 + j] = bj + hsum2(a10) + hsum2(a11);
            __syncthreads();
        }
        // Publish timestep t: every thread fences its STGs to gpu scope, the
        // block barrier orders them before thread 0's release store.
        __threadfence();
        __syncthreads();
        if (j == 0) st_rel(&g_ready[t], 1);
    }
}

// ---------------------------------------------------------------------------
// Scan role: blocks 0..31, one per batch element. Identical to R5's scan plus
// an amortized readiness check (frontier F) before each cp.async refill.
// ---------------------------------------------------------------------------
__device__ __forceinline__ void scan_role(const void* __restrict__ resets,
                                          const float* __restrict__ Wh,
                                          const float* __restrict__ bhn,
                                          float* __restrict__ ys, int b) {
    __shared__ __align__(16) float h[2][DD];
    __shared__ float hh[D3];
    __shared__ __align__(16) float xstage[NSTAGE][D3];
    __shared__ unsigned char srst[TT];

    const int j = threadIdx.x;
    const int d = j & 127;
    const int g = j >> 7;
    const int mode = g_reset_mode;

    unsigned long long w2[64];
#pragma unroll
    for (int k = 0; k < 64; k++)
        w2[k] = pack2(Wh[(2 * k) * D3 + j], Wh[(2 * k + 1) * D3 + j]);
    const float bn = (g == 2) ? bhn[d] : 0.0f;

    if (j < DD) h[0][j] = 0.0f;

    for (int t = j; t < TT; t += 384)
        srst[t] = (unsigned char)read_reset(resets, t * BB + b, mode);

    // Prime the ring: stages 0..NSTAGE-1 (poll exact flag; only warmup cost).
    for (int s = 0; s < NSTAGE; s++) {
        while (ld_acq(&g_ready[s]) == 0) __nanosleep(64);
        if (j < 96)
            cp_async16(&xstage[s][j * 4],
                       g_xi + ((size_t)s * BB + b) * D3 + j * 4);
        asm volatile("cp.async.commit_group;" ::: "memory");
    }
    __syncthreads();

    int F = NSTAGE;  // xi rows < F known complete (uniform across threads)
    int p = 0;
    for (int t = 0; t < TT; t++) {
        const int st = t & (NSTAGE - 1);
        const int rst = srst[t];

        // hh[j] = (g==2 ? bhn : 0) + <Wh[:,j], h>, dot skipped on reset.
        unsigned long long a0 = 0ull, a1 = 0ull, a2 = 0ull, a3 = 0ull;
        const ulonglong2* h2 = (const ulonglong2*)h[p];
#pragma unroll
        for (int k = 0; k < 16; k++) {
            ulonglong2 va = h2[2 * k];
            ulonglong2 vb = h2[2 * k + 1];
            fma2(a0, w2[4 * k + 0], va.x);
            fma2(a1, w2[4 * k + 1], va.y);
            fma2(a2, w2[4 * k + 2], vb.x);
            fma2(a3, w2[4 * k + 3], vb.y);
        }
        float dot = (hsum2(a0) + hsum2(a1)) + (hsum2(a2) + hsum2(a3));
        hh[j] = bn + (rst ? 0.0f : dot);

        // Stage t (oldest of NSTAGE pending groups) must be complete.
        asm volatile("cp.async.wait_group %0;" :: "n"(NSTAGE - 1) : "memory");
        __syncthreads();  // B1: hh + stage st published.

        if (j < DD) {
            const float* xi_s = xstage[st];
            float sr = xi_s[d]       + hh[d];          // xr + hr
            float sz = xi_s[128 + d] + hh[128 + d];    // xz + hz
            float sn = hh[256 + d];                    // hn + bhn
            float rg = __fdividef(1.0f, 1.0f + __expf(-sr));
            float zg = __fdividef(1.0f, 1.0f + __expf(-sz));
            float ar = xi_s[256 + d] + rg * sn;        // xn + r*(hn+bhn)
            float ng = __fdividef(2.0f, 1.0f + __expf(-2.0f * ar)) - 1.0f;
            float hp = rst ? 0.0f : h[p][d];
            float nh = (1.0f - zg) * ng + zg * hp;
            h[p ^ 1][d] = nh;
            ys[((size_t)t * BB + b) * DD + d] = nh;
        }
        __syncthreads();  // B2: new h published; slot st fully consumed.

        // Refill slot st with stage t+NSTAGE. Amortized readiness check: one
        // acquire-load per ~256 steps in steady state (producer runs ~10x
        // faster), so the ~234-cyc L2 poll stays off the critical path.
        const int need = t + NSTAGE;
        if (need < TT) {
            if (need >= F) {
                int probe_t = need + 256;
                if (probe_t > TT - 1) probe_t = TT - 1;
                if (ld_acq(&g_ready[probe_t])) {
                    F = probe_t + 1;
                } else {
                    while (ld_acq(&g_ready[need]) == 0) __nanosleep(64);
                    F = need + 1;
                }
            }
            if (j < 96)
                cp_async16(&xstage[st][j * 4],
                           g_xi + ((size_t)need * BB + b) * D3 + j * 4);
        }
        asm volatile("cp.async.commit_group;" ::: "memory");

        p ^= 1;
    }
}

// ---------------------------------------------------------------------------
// Fused kernel: blocks 0..31 scan, blocks 32.. run the producer GEMM.
// w2[64] (128 regs/thread) guarantees occupancy 1 CTA/SM, so with
// grid == #SMs every CTA is resident in wave 1 — no producer/consumer
// scheduling deadlock is possible.
// ---------------------------------------------------------------------------
__global__ __launch_bounds__(384, 1)
void fused_kernel(const float* __restrict__ x,
                  const void* __restrict__ resets,
                  const float* __restrict__ Wi,
                  const float* __restrict__ bi,
                  const float* __restrict__ Wh,
                  const float* __restrict__ bhn,
                  float* __restrict__ ys,
                  int ngemm) {
    if (blockIdx.x < BB)
        scan_role(resets, Wh, bhn, ys, blockIdx.x);
    else
        gemm_role(x, Wi, bi, blockIdx.x - BB, ngemm);
}

// ---------------------------------------------------------------------------
extern "C" void kernel_launch(void* const* d_in, const int* in_sizes, int n_in,
                              void* d_out, int out_size) {
    const float* x      = (const float*)d_in[0];
    const void*  resets = d_in[1];
    const float* Wi     = (const float*)d_in[2];
    const float* bi     = (const float*)d_in[3];
    const float* Wh     = (const float*)d_in[4];
    const float* bhn    = (const float*)d_in[5];
    float* ys = (float*)d_out;

    int dev = 0, nsm = 148;
    cudaGetDevice(&dev);
    cudaDeviceGetAttribute(&nsm, cudaDevAttrMultiProcessorCount, dev);
    if (nsm < BB + 1) nsm = BB + 1;  // paranoia; never on this part

    probe_clear_kernel<<<1, 256>>>((const unsigned int*)resets);
    fused_kernel<<<nsm, 384>>>(x, resets, Wi, bi, Wh, bhn, ys, nsm - BB);
}

// round 7
// speedup vs baseline: 1.9918x; 1.0018x over previous
#include <cuda_runtime.h>

#define TT 4096
#define BB 32
#define DD 128
#define D3 384
#define NSTAGE 8

// Scratch for xi = x @ Wi + bi : [T, B, 3D] fp32 = 201 MB.
__device__ float g_xi[(size_t)TT * BB * D3];
__device__ int g_reset_mode;  // 0 = int32, 1 = float32, 2 = uint8/bool
__device__ int g_ready[TT];   // per-timestep xi completion flags

// ---------------------------------------------------------------------------
// Helpers
// ---------------------------------------------------------------------------
__device__ __forceinline__ int read_reset(const void* r, int idx, int mode) {
    if (mode == 0) return ((const int*)r)[idx] != 0;
    if (mode == 1) return ((const float*)r)[idx] != 0.0f;
    return ((const unsigned char*)r)[idx] != 0;
}

__device__ __forceinline__ unsigned long long pack2(float lo, float hi) {
    unsigned long long p;
    asm("mov.b64 %0, {%1, %2};" : "=l"(p) : "f"(lo), "f"(hi));
    return p;
}

__device__ __forceinline__ void fma2(unsigned long long& acc,
                                     unsigned long long a,
                                     unsigned long long b) {
    asm("fma.rn.f32x2 %0, %1, %2, %0;" : "+l"(acc) : "l"(a), "l"(b));
}

__device__ __forceinline__ float hsum2(unsigned long long a) {
    float lo, hi;
    asm("mov.b64 {%0, %1}, %2;" : "=f"(lo), "=f"(hi) : "l"(a));
    return lo + hi;
}

__device__ __forceinline__ void cp_async16(void* smem_dst, const void* gmem_src) {
    unsigned s = (unsigned)__cvta_generic_to_shared(smem_dst);
    asm volatile("cp.async.cg.shared.global [%0], [%1], 16;"
                 :: "r"(s), "l"(gmem_src) : "memory");
}

__device__ __forceinline__ int ld_acq(const int* p) {
    int v;
    asm volatile("ld.acquire.gpu.b32 %0, [%1];" : "=r"(v) : "l"(p) : "memory");
    return v;
}

__device__ __forceinline__ void st_rel(int* p, int v) {
    asm volatile("st.release.gpu.b32 [%0], %1;" :: "l"(p), "r"(v) : "memory");
}

// ---------------------------------------------------------------------------
// Probe resets dtype (reads 128 KB — in-bounds for every candidate layout)
// and clear the per-timestep ready flags for this replay.
// ---------------------------------------------------------------------------
__global__ void probe_clear_kernel(const unsigned int* __restrict__ r) {
    for (int i = threadIdx.x; i < TT; i += blockDim.x) g_ready[i] = 0;
    __shared__ int s_not01, s_notf;
    if (threadIdx.x == 0) { s_not01 = 0; s_notf = 0; }
    __syncthreads();
    int not01 = 0, notf = 0;
    for (int i = threadIdx.x; i < 32768; i += blockDim.x) {
        unsigned v = r[i];
        if (v != 0u && v != 1u) not01 = 1;
        if (v != 0u && v != 0x3F800000u) notf = 1;
    }
    if (not01) atomicOr(&s_not01, 1);
    if (notf)  atomicOr(&s_notf, 1);
    __syncthreads();
    if (threadIdx.x == 0)
        g_reset_mode = (!s_not01) ? 0 : ((!s_notf) ? 1 : 2);
}

// ---------------------------------------------------------------------------
// GEMM role: blocks 32..grid-1. Block gb owns timesteps t = gb, gb+ngemm, ...
// For each t it computes xi rows [t*32, t*32+32) and publishes g_ready[t].
// ---------------------------------------------------------------------------
__device__ __forceinline__ void gemm_role(const float* __restrict__ x,
                                          const float* __restrict__ Wi,
                                          const float* __restrict__ bi,
                                          int gb, int ngemm) {
    __shared__ __align__(16) float xs[2][DD];
    const int j = threadIdx.x;

    unsigned long long w2[64];
#pragma unroll
    for (int k = 0; k < 64; k++)
        w2[k] = pack2(Wi[(2 * k) * D3 + j], Wi[(2 * k + 1) * D3 + j]);
    const float bj = bi[j];

    for (int t = gb; t < TT; t += ngemm) {
        const int r0 = t * BB;
        for (int rp = 0; rp < BB; rp += 2) {
            const int r = r0 + rp;
            if (j < 256)
                xs[j >> 7][j & 127] = x[(size_t)(r + (j >> 7)) * DD + (j & 127)];
            __syncthreads();

            unsigned long long a00 = 0ull, a01 = 0ull, a10 = 0ull, a11 = 0ull;
            const ulonglong2* x0 = (const ulonglong2*)xs[0];
            const ulonglong2* x1 = (const ulonglong2*)xs[1];
#pragma unroll
            for (int k = 0; k < 32; k++) {
                ulonglong2 v0 = x0[k];
                ulonglong2 v1 = x1[k];
                fma2(a00, w2[2 * k],     v0.x);
                fma2(a01, w2[2 * k + 1], v0.y);
                fma2(a10, w2[2 * k],     v1.x);
                fma2(a11, w2[2 * k + 1], v1.y);
            }
            g_xi[(size_t)r * D3 + j]       = bj + hsum2(a00) + hsum2(a01);
            g_xi[(size_t)(r + 1) * D3 + j] = bj + hsum2(a10) + hsum2(a11);
            __syncthreads();
        }
        // Publish timestep t: every thread fences its STGs to gpu scope, the
        // block barrier orders them before thread 0's release store.
        __threadfence();
        __syncthreads();
        if (j == 0) st_rel(&g_ready[t], 1);
    }
}

// ---------------------------------------------------------------------------
// Scan role: blocks 0..31, one per batch element. Identical to R5's scan plus
// an amortized readiness check (frontier F) before each cp.async refill.
// ---------------------------------------------------------------------------
__device__ __forceinline__ void scan_role(const void* __restrict__ resets,
                                          const float* __restrict__ Wh,
                                          const float* __restrict__ bhn,
                                          float* __restrict__ ys, int b) {
    __shared__ __align__(16) float h[2][DD];
    __shared__ float hh[D3];
    __shared__ __align__(16) float xstage[NSTAGE][D3];
    __shared__ unsigned char srst[TT];

    const int j = threadIdx.x;
    const int d = j & 127;
    const int g = j >> 7;
    const int mode = g_reset_mode;

    unsigned long long w2[64];
#pragma unroll
    for (int k = 0; k < 64; k++)
        w2[k] = pack2(Wh[(2 * k) * D3 + j], Wh[(2 * k + 1) * D3 + j]);
    const float bn = (g == 2) ? bhn[d] : 0.0f;

    if (j < DD) h[0][j] = 0.0f;

    for (int t = j; t < TT; t += 384)
        srst[t] = (unsigned char)read_reset(resets, t * BB + b, mode);

    // Prime the ring: stages 0..NSTAGE-1 (poll exact flag; only warmup cost).
    for (int s = 0; s < NSTAGE; s++) {
        while (ld_acq(&g_ready[s]) == 0) __nanosleep(64);
        if (j < 96)
            cp_async16(&xstage[s][j * 4],
                       g_xi + ((size_t)s * BB + b) * D3 + j * 4);
        asm volatile("cp.async.commit_group;" ::: "memory");
    }
    __syncthreads();

    int F = NSTAGE;  // xi rows < F known complete (uniform across threads)
    int p = 0;
    for (int t = 0; t < TT; t++) {
        const int st = t & (NSTAGE - 1);
        const int rst = srst[t];

        // hh[j] = (g==2 ? bhn : 0) + <Wh[:,j], h>, dot skipped on reset.
        unsigned long long a0 = 0ull, a1 = 0ull, a2 = 0ull, a3 = 0ull;
        const ulonglong2* h2 = (const ulonglong2*)h[p];
#pragma unroll
        for (int k = 0; k < 16; k++) {
            ulonglong2 va = h2[2 * k];
            ulonglong2 vb = h2[2 * k + 1];
            fma2(a0, w2[4 * k + 0], va.x);
            fma2(a1, w2[4 * k + 1], va.y);
            fma2(a2, w2[4 * k + 2], vb.x);
            fma2(a3, w2[4 * k + 3], vb.y);
        }
        float dot = (hsum2(a0) + hsum2(a1)) + (hsum2(a2) + hsum2(a3));
        hh[j] = bn + (rst ? 0.0f : dot);

        // Stage t (oldest of NSTAGE pending groups) must be complete.
        asm volatile("cp.async.wait_group %0;" :: "n"(NSTAGE - 1) : "memory");
        __syncthreads();  // B1: hh + stage st published.

        if (j < DD) {
            const float* xi_s = xstage[st];
            float sr = xi_s[d]       + hh[d];          // xr + hr
            float sz = xi_s[128 + d] + hh[128 + d];    // xz + hz
            float sn = hh[256 + d];                    // hn + bhn
            float rg = __fdividef(1.0f, 1.0f + __expf(-sr));
            float zg = __fdividef(1.0f, 1.0f + __expf(-sz));
            float ar = xi_s[256 + d] + rg * sn;        // xn + r*(hn+bhn)
            float ng = __fdividef(2.0f, 1.0f + __expf(-2.0f * ar)) - 1.0f;
            float hp = rst ? 0.0f : h[p][d];
            float nh = (1.0f - zg) * ng + zg * hp;
            h[p ^ 1][d] = nh;
            ys[((size_t)t * BB + b) * DD + d] = nh;
        }
        __syncthreads();  // B2: new h published; slot st fully consumed.

        // Refill slot st with stage t+NSTAGE. Amortized readiness check: one
        // acquire-load per ~256 steps in steady state (producer runs ~10x
        // faster), so the ~234-cyc L2 poll stays off the critical path.
        const int need = t + NSTAGE;
        if (need < TT) {
            if (need >= F) {
                int probe_t = need + 256;
                if (probe_t > TT - 1) probe_t = TT - 1;
                if (ld_acq(&g_ready[probe_t])) {
                    F = probe_t + 1;
                } else {
                    while (ld_acq(&g_ready[need]) == 0) __nanosleep(64);
                    F = need + 1;
                }
            }
            if (j < 96)
                cp_async16(&xstage[st][j * 4],
                           g_xi + ((size_t)need * BB + b) * D3 + j * 4);
        }
        asm volatile("cp.async.commit_group;" ::: "memory");

        p ^= 1;
    }
}

// ---------------------------------------------------------------------------
// Fused kernel: blocks 0..31 scan, blocks 32.. run the producer GEMM.
// w2[64] (128 regs/thread) guarantees occupancy 1 CTA/SM, so with
// grid == #SMs every CTA is resident in wave 1 — no producer/consumer
// scheduling deadlock is possible.
// ---------------------------------------------------------------------------
__global__ __launch_bounds__(384, 1)
void fused_kernel(const float* __restrict__ x,
                  const void* __restrict__ resets,
                  const float* __restrict__ Wi,
                  const float* __restrict__ bi,
                  const float* __restrict__ Wh,
                  const float* __restrict__ bhn,
                  float* __restrict__ ys,
                  int ngemm) {
    if (blockIdx.x < BB)
        scan_role(resets, Wh, bhn, ys, blockIdx.x);
    else
        gemm_role(x, Wi, bi, blockIdx.x - BB, ngemm);
}

// ---------------------------------------------------------------------------
extern "C" void kernel_launch(void* const* d_in, const int* in_sizes, int n_in,
                              void* d_out, int out_size) {
    const float* x      = (const float*)d_in[0];
    const void*  resets = d_in[1];
    const float* Wi     = (const float*)d_in[2];
    const float* bi     = (const float*)d_in[3];
    const float* Wh     = (const float*)d_in[4];
    const float* bhn    = (const float*)d_in[5];
    float* ys = (float*)d_out;

    int dev = 0, nsm = 148;
    cudaGetDevice(&dev);
    cudaDeviceGetAttribute(&nsm, cudaDevAttrMultiProcessorCount, dev);
    if (nsm < BB + 1) nsm = BB + 1;  // paranoia; never on this part

    probe_clear_kernel<<<1, 256>>>((const unsigned int*)resets);
    fused_kernel<<<nsm, 384>>>(x, resets, Wi, bi, Wh, bhn, ys, nsm - BB);
}

// round 9
// speedup vs baseline: 2.0730x; 1.0408x over previous
#include <cuda_runtime.h>

#define TT 4096
#define BB 32
#define DD 128
#define D3 384
#define NSTAGE 16

// Scratch for xi = x @ Wi + bi : [T, B, 3D] fp32 = 201 MB.
__device__ float g_xi[(size_t)TT * BB * D3];
__device__ int g_reset_mode;  // 0 = int32, 1 = float32, 2 = uint8/bool
__device__ int g_ready[TT];   // per-timestep xi completion flags

// ---------------------------------------------------------------------------
// Helpers
// ---------------------------------------------------------------------------
__device__ __forceinline__ int read_reset(const void* r, int idx, int mode) {
    if (mode == 0) return ((const int*)r)[idx] != 0;
    if (mode == 1) return ((const float*)r)[idx] != 0.0f;
    return ((const unsigned char*)r)[idx] != 0;
}

__device__ __forceinline__ unsigned long long pack2(float lo, float hi) {
    unsigned long long p;
    asm("mov.b64 %0, {%1, %2};" : "=l"(p) : "f"(lo), "f"(hi));
    return p;
}

__device__ __forceinline__ void fma2(unsigned long long& acc,
                                     unsigned long long a,
                                     unsigned long long b) {
    asm("fma.rn.f32x2 %0, %1, %2, %0;" : "+l"(acc) : "l"(a), "l"(b));
}

__device__ __forceinline__ unsigned long long add2(unsigned long long a,
                                                   unsigned long long b) {
    unsigned long long r;
    asm("add.rn.f32x2 %0, %1, %2;" : "=l"(r) : "l"(a), "l"(b));
    return r;
}

__device__ __forceinline__ float hsum2(unsigned long long a) {
    float lo, hi;
    asm("mov.b64 {%0, %1}, %2;" : "=f"(lo), "=f"(hi) : "l"(a));
    return lo + hi;
}

__device__ __forceinline__ void cp_async16(void* smem_dst, const void* gmem_src) {
    unsigned s = (unsigned)__cvta_generic_to_shared(smem_dst);
    asm volatile("cp.async.cg.shared.global [%0], [%1], 16;"
                 :: "r"(s), "l"(gmem_src) : "memory");
}

__device__ __forceinline__ int ld_acq(const int* p) {
    int v;
    asm volatile("ld.acquire.gpu.b32 %0, [%1];" : "=r"(v) : "l"(p) : "memory");
    return v;
}

__device__ __forceinline__ void st_rel(int* p, int v) {
    asm volatile("st.release.gpu.b32 [%0], %1;" :: "l"(p), "r"(v) : "memory");
}

// ---------------------------------------------------------------------------
// Probe resets dtype (reads 128 KB — in-bounds for every candidate layout)
// and clear the per-timestep ready flags for this replay.
// ---------------------------------------------------------------------------
__global__ void probe_clear_kernel(const unsigned int* __restrict__ r) {
    for (int i = threadIdx.x; i < TT; i += blockDim.x) g_ready[i] = 0;
    __shared__ int s_not01, s_notf;
    if (threadIdx.x == 0) { s_not01 = 0; s_notf = 0; }
    __syncthreads();
    int not01 = 0, notf = 0;
    for (int i = threadIdx.x; i < 32768; i += blockDim.x) {
        unsigned v = r[i];
        if (v != 0u && v != 1u) not01 = 1;
        if (v != 0u && v != 0x3F800000u) notf = 1;
    }
    if (not01) atomicOr(&s_not01, 1);
    if (notf)  atomicOr(&s_notf, 1);
    __syncthreads();
    if (threadIdx.x == 0)
        g_reset_mode = (!s_not01) ? 0 : ((!s_notf) ? 1 : 2);
}

// ---------------------------------------------------------------------------
// GEMM role: blocks 32..grid-1. Block gb owns timesteps t = gb, gb+ngemm, ...
// ---------------------------------------------------------------------------
__device__ __forceinline__ void gemm_role(const float* __restrict__ x,
                                          const float* __restrict__ Wi,
                                          const float* __restrict__ bi,
                                          int gb, int ngemm) {
    __shared__ __align__(16) float xs[2][DD];
    const int j = threadIdx.x;

    unsigned long long w2[64];
#pragma unroll
    for (int k = 0; k < 64; k++)
        w2[k] = pack2(Wi[(2 * k) * D3 + j], Wi[(2 * k + 1) * D3 + j]);
    const float bj = bi[j];

    for (int t = gb; t < TT; t += ngemm) {
        const int r0 = t * BB;
        for (int rp = 0; rp < BB; rp += 2) {
            const int r = r0 + rp;
            if (j < 256)
                xs[j >> 7][j & 127] = x[(size_t)(r + (j >> 7)) * DD + (j & 127)];
            __syncthreads();

            unsigned long long a00 = 0ull, a01 = 0ull, a10 = 0ull, a11 = 0ull;
            const ulonglong2* x0 = (const ulonglong2*)xs[0];
            const ulonglong2* x1 = (const ulonglong2*)xs[1];
#pragma unroll
            for (int k = 0; k < 32; k++) {
                ulonglong2 v0 = x0[k];
                ulonglong2 v1 = x1[k];
                fma2(a00, w2[2 * k],     v0.x);
                fma2(a01, w2[2 * k + 1], v0.y);
                fma2(a10, w2[2 * k],     v1.x);
                fma2(a11, w2[2 * k + 1], v1.y);
            }
            g_xi[(size_t)r * D3 + j]       = bj + hsum2(add2(a00, a01));
            g_xi[(size_t)(r + 1) * D3 + j] = bj + hsum2(add2(a10, a11));
            __syncthreads();
        }
        __threadfence();
        __syncthreads();
        if (j == 0) st_rel(&g_ready[t], 1);
    }
}

// ---------------------------------------------------------------------------
// Scan role: blocks 0..31, one per batch element. Warp-specialized step:
//   dot phase (all 12 warps): hh[j] = <Wh[:,j], h[p]>  (unconditional; gate
//     warps additionally preload xi/reset for this step into registers)
//   B1
//   window:  warps 0-3  -> gate math (+reset selects), write h[p^1]
//            warps 4-7  -> store ys for step t-1 from stable h[p]
//            warps 8-10 -> frontier check + cp.async refill of slot st
//                          (+commit+wait: exclusive owners of group state)
//   B2
// ---------------------------------------------------------------------------
__device__ __forceinline__ void scan_role(const void* __restrict__ resets,
                                          const float* __restrict__ Wh,
                                          const float* __restrict__ bhn,
                                          float* __restrict__ ys, int b) {
    __shared__ __align__(16) float h[2][DD];
    __shared__ float hh[D3];
    __shared__ __align__(16) float xstage[NSTAGE][D3];
    __shared__ unsigned char srst[TT];

    const int j = threadIdx.x;
    const int d = j & 127;
    const int mode = g_reset_mode;

    const bool is_gate = (j < 128);
    const bool is_ys   = (j >= 128 && j < 256);
    const bool is_refl = (j >= 256 && j < 352);
    const int  rl      = j - 256;  // refill lane 0..95

    unsigned long long w2[64];
#pragma unroll
    for (int k = 0; k < 64; k++)
        w2[k] = pack2(Wh[(2 * k) * D3 + j], Wh[(2 * k + 1) * D3 + j]);
    const float bn = is_gate ? bhn[d] : 0.0f;

    if (j < DD) h[0][j] = 0.0f;

    for (int t = j; t < TT; t += 384)
        srst[t] = (unsigned char)read_reset(resets, t * BB + b, mode);

    // Prime the ring (refill warps own all cp.async group state).
    if (is_refl) {
        for (int s = 0; s < NSTAGE; s++) {
            while (ld_acq(&g_ready[s]) == 0) __nanosleep(64);
            cp_async16(&xstage[s][rl * 4],
                       g_xi + ((size_t)s * BB + b) * D3 + rl * 4);
            asm volatile("cp.async.commit_group;" ::: "memory");
        }
        // Slot 0 must be complete before the t=0 gate preload reads it.
        asm volatile("cp.async.wait_group %0;" :: "n"(NSTAGE - 1) : "memory");
    }
    __syncthreads();

    // Running pointers (strength-reduced). yp points at the NEXT row to write
    // (row t-1 is written at iteration t, then yp advances one row).
    float* yp = is_ys ? (ys + (size_t)b * DD + (j - 128)) : ys;
    const float* rp = g_xi + ((size_t)NSTAGE * BB + b) * D3 + rl * 4;

    int F = NSTAGE;  // uniform across refill warps
    int p = 0;
    for (int t = 0; t < TT; t++) {
        const int st = t & (NSTAGE - 1);

        // Gate warps preload this step's xi + reset flag (registers), so the
        // refill warps may overwrite slot st during the window.
        float xr = 0.0f, xz = 0.0f, xn = 0.0f;
        int rst = 0;
        if (is_gate) {
            const float* xi_s = xstage[st];
            xr = xi_s[d];
            xz = xi_s[128 + d];
            xn = xi_s[256 + d];
            rst = srst[t];
        }

        // Unconditional dot: hh[j] = <Wh[:,j], h[p]>.
        unsigned long long a0 = 0ull, a1 = 0ull, a2 = 0ull, a3 = 0ull;
        const ulonglong2* h2 = (const ulonglong2*)h[p];
#pragma unroll
        for (int k = 0; k < 16; k++) {
            ulonglong2 va = h2[2 * k];
            ulonglong2 vb = h2[2 * k + 1];
            fma2(a0, w2[4 * k + 0], va.x);
            fma2(a1, w2[4 * k + 1], va.y);
            fma2(a2, w2[4 * k + 2], vb.x);
            fma2(a3, w2[4 * k + 3], vb.y);
        }
        hh[j] = hsum2(add2(add2(a0, a1), add2(a2, a3)));
        __syncthreads();  // B1: hh published; slot-st reads done.

        if (is_gate) {
            float hr = rst ? 0.0f : hh[d];
            float hz = rst ? 0.0f : hh[128 + d];
            float sn = (rst ? 0.0f : hh[256 + d]) + bn;  // hn + bhn
            float rg = __fdividef(1.0f, 1.0f + __expf(-(xr + hr)));
            float zg = __fdividef(1.0f, 1.0f + __expf(-(xz + hz)));
            float ar = xn + rg * sn;
            float ng = __fdividef(2.0f, 1.0f + __expf(-2.0f * ar)) - 1.0f;
            float hp = rst ? 0.0f : h[p][d];
            h[p ^ 1][d] = (1.0f - zg) * ng + zg * hp;
        } else if (is_ys) {
            if (t > 0) {                      // h[p] == output of step t-1
                *yp = h[p][j - 128];          // row t-1
                yp += BB * DD;                // advance only when written
            }
        } else if (is_refl) {
            const int need = t + NSTAGE;
            if (need < TT) {
                if (need >= F) {
                    int probe_t = need + 256;
                    if (probe_t > TT - 1) probe_t = TT - 1;
                    if (ld_acq(&g_ready[probe_t])) {
                        F = probe_t + 1;
                    } else {
                        while (ld_acq(&g_ready[need]) == 0) __nanosleep(64);
                        F = need + 1;
                    }
                }
                cp_async16(&xstage[st][rl * 4], rp);
            }
            rp += (size_t)BB * D3;
            asm volatile("cp.async.commit_group;" ::: "memory");
            // Next step's slot (oldest pending group) must be complete
            // before this thread's B2 arrival publishes it.
            asm volatile("cp.async.wait_group %0;" :: "n"(NSTAGE - 1) : "memory");
        }
        __syncthreads();  // B2: new h (+ next slot) published.

        p ^= 1;
    }

    if (is_ys) *yp = h[p][j - 128];  // row TT-1 (yp advanced TT-1 times)
}

// ---------------------------------------------------------------------------
// Fused kernel: blocks 0..31 scan, blocks 32.. run the producer GEMM.
// >=128 regs/thread -> 1 CTA/SM; grid == #SMs => all CTAs resident in wave 1,
// so the producer/consumer handshake cannot deadlock.
// ---------------------------------------------------------------------------
__global__ __launch_bounds__(384, 1)
void fused_kernel(const float* __restrict__ x,
                  const void* __restrict__ resets,
                  const float* __restrict__ Wi,
                  const float* __restrict__ bi,
                  const float* __restrict__ Wh,
                  const float* __restrict__ bhn,
                  float* __restrict__ ys,
                  int ngemm) {
    if (blockIdx.x < BB)
        scan_role(resets, Wh, bhn, ys, blockIdx.x);
    else
        gemm_role(x, Wi, bi, blockIdx.x - BB, ngemm);
}

// ---------------------------------------------------------------------------
extern "C" void kernel_launch(void* const* d_in, const int* in_sizes, int n_in,
                              void* d_out, int out_size) {
    const float* x      = (const float*)d_in[0];
    const void*  resets = d_in[1];
    const float* Wi     = (const float*)d_in[2];
    const float* bi     = (const float*)d_in[3];
    const float* Wh     = (const float*)d_in[4];
    const float* bhn    = (const float*)d_in[5];
    float* ys = (float*)d_out;

    int dev = 0, nsm = 148;
    cudaGetDevice(&dev);
    cudaDeviceGetAttribute(&nsm, cudaDevAttrMultiProcessorCount, dev);
    if (nsm < BB + 1) nsm = BB + 1;

    probe_clear_kernel<<<1, 256>>>((const unsigned int*)resets);
    fused_kernel<<<nsm, 384>>>(x, resets, Wi, bi, Wh, bhn, ys, nsm - BB);
}